// round 6
// baseline (speedup 1.0000x reference)
#include <cuda_runtime.h>
#include <math.h>

#define TPB    256
#define NWARP  (TPB / 32)          // 8 preds per block (warp per pred)
#define MAXM   1024
#define G      8
#define QCAP   2048
#define WMIN   (-50.0f)
#define CELLSZ 12.5f
#define INVCEL (1.0f / CELLSZ)

// GT data precomputed by prep_kernel:
__device__ float4 g_gtA[MAXM];     // (cx, cy, radius, area)
__device__ float4 g_gtB[MAXM];     // (cos, sin, hx, hy)
__device__ int    g_start[G * G + 1];
__device__ unsigned short g_list[MAXM];
__device__ float  g_rbmax;
__device__ float  g_acc;           // self-resetting accumulator
__device__ int    g_done;          // self-resetting block counter

__device__ __forceinline__ int clampi(int v, int lo, int hi) {
    return v < lo ? lo : (v > hi ? hi : v);
}

// ---------- Prep: bin GT boxes into grid + precompute SoA (1 block) ----------
__global__ void prep_kernel(const float* __restrict__ box_gt, int M) {
    __shared__ int cnt[G * G];
    __shared__ int off[G * G + 1];
    __shared__ short cellof[MAXM];
    __shared__ int srb;

    int tid = threadIdx.x;
    for (int c = tid; c < G * G; c += blockDim.x) cnt[c] = 0;
    if (tid == 0) srb = 0;
    __syncthreads();

    for (int j = tid; j < M; j += blockDim.x) {
        const float* b = box_gt + j * 7;
        float x = b[0], y = b[1], dx = b[3], dy = b[4], yaw = b[6];
        float s, c;
        __sincosf(yaw, &s, &c);
        float rb = 0.5f * sqrtf(dx * dx + dy * dy);
        g_gtA[j] = make_float4(x, y, rb, dx * dy);
        g_gtB[j] = make_float4(c, s, 0.5f * dx, 0.5f * dy);
        atomicMax(&srb, __float_as_int(rb));
        int cx = clampi((int)floorf((x - WMIN) * INVCEL), 0, G - 1);
        int cy = clampi((int)floorf((y - WMIN) * INVCEL), 0, G - 1);
        int cell = cy * G + cx;
        cellof[j] = (short)cell;
        atomicAdd(&cnt[cell], 1);
    }
    __syncthreads();

    if (tid == 0) {
        int acc = 0;
        for (int c = 0; c < G * G; c++) { off[c] = acc; acc += cnt[c]; }
        off[G * G] = acc;
        g_rbmax = __int_as_float(srb);
    }
    __syncthreads();

    for (int c = tid; c <= G * G; c += blockDim.x) g_start[c] = off[c];
    __syncthreads();

    for (int j = tid; j < M; j += blockDim.x) {
        int pos = atomicAdd(&off[cellof[j]], 1);
        g_list[pos] = (unsigned short)j;
    }
}

// Branchless Liang-Barsky segment clip vs box [-hx,hx]x[-hy,hy] (B-local
// param frame); endpoints evaluated in the common o_B-relative frame.
__device__ __forceinline__ float seg_contrib(
    float px, float py, float dx, float dy, float hx, float hy,
    float pwx, float pwy, float dwx, float dwy)
{
    float ix = __fdividef(1.0f, dx);
    float ta = (-hx - px) * ix, tb = (hx - px) * ix;
    float t0 = fmaxf(0.0f, fminf(ta, tb));
    float t1 = fminf(1.0f, fmaxf(ta, tb));
    float iy = __fdividef(1.0f, dy);
    float tc = (-hy - py) * iy, td = (hy - py) * iy;
    t0 = fmaxf(t0, fminf(tc, td));
    t1 = fminf(t1, fmaxf(tc, td));

    float sx = fmaf(t0, dwx, pwx), sy = fmaf(t0, dwy, pwy);
    float ex = fmaf(t1, dwx, pwx), ey = fmaf(t1, dwy, pwy);
    float cr = sx * ey - sy * ex;
    return (t1 >= t0) ? cr : 0.0f;
}

// Full pair IoU: sp = 16-float pred record in smem, (A4,B4) = gt SoA.
__device__ float pair_iou(const float* __restrict__ sp, float4 A4, float4 B4) {
    float ppx = sp[8], ppy = sp[9];
    float phx = sp[10], phy = sp[11];
    float psa = sp[12], pca = sp[13];
    float area_a = sp[14];

    float bx = A4.x, by = A4.y, area_b = A4.w;
    float cb = B4.x, sb = B4.y, hbx = B4.z, hby = B4.w;

    float rax[4], ray[4], lax[4], lay[4];
    #pragma unroll
    for (int kk = 0; kk < 4; kk++) {
        rax[kk] = sp[kk] - bx;
        ray[kk] = sp[4 + kk] - by;
        lax[kk] =  cb * rax[kk] + sb * ray[kk];
        lay[kk] = -sb * rax[kk] + cb * ray[kk];
    }

    float tot = 0.0f;
    #pragma unroll
    for (int kk = 0; kk < 4; kk++) {
        int kn = (kk + 1) & 3;
        tot += seg_contrib(lax[kk], lay[kk],
                           lax[kn] - lax[kk], lay[kn] - lay[kk],
                           hbx, hby,
                           rax[kk], ray[kk],
                           rax[kn] - rax[kk], ray[kn] - ray[kk]);
    }

    const float lbx[4] = {hbx, -hbx, -hbx, hbx};
    const float lby[4] = {hby, hby, -hby, -hby};
    float rbx[4], rby[4], qx[4], qy[4];
    float ox = bx - ppx, oy = by - ppy;
    #pragma unroll
    for (int kk = 0; kk < 4; kk++) {
        rbx[kk] = cb * lbx[kk] - sb * lby[kk];
        rby[kk] = sb * lbx[kk] + cb * lby[kk];
        float tx = rbx[kk] + ox, ty = rby[kk] + oy;
        qx[kk] =  pca * tx + psa * ty;
        qy[kk] = -psa * tx + pca * ty;
    }
    #pragma unroll
    for (int kk = 0; kk < 4; kk++) {
        int kn = (kk + 1) & 3;
        tot += seg_contrib(qx[kk], qy[kk],
                           qx[kn] - qx[kk], qy[kn] - qy[kk],
                           phx, phy,
                           rbx[kk], rby[kk],
                           rbx[kn] - rbx[kk], rby[kn] - rby[kk]);
    }

    float inter = 0.5f * fabsf(tot);
    float uni = fmaxf(area_a + area_b - inter, 1e-8f);
    return inter / uni;
}

// ---------- Main: warp-per-pred scan over binned candidates ----------
__global__ void __launch_bounds__(TPB)
iou_loss_kernel(const float* __restrict__ iou_pred,
                const float* __restrict__ box_pred,
                const void* __restrict__ ntp_raw,
                float* __restrict__ out,
                int N, int M, int out_size)
{
    __shared__ unsigned short q[QCAP];
    __shared__ int qcnt;
    __shared__ int sbest[NWARP];             // float bits of best iou (>= 0)
    __shared__ float spred[NWARP][16];       // wx[4] wy[4] px py hx hy sa ca area

    const int tid   = threadIdx.x;
    const int lane  = tid & 31;
    const int slot  = tid >> 5;
    const int p     = blockIdx.x * NWARP + slot;
    const bool valid = (p < N);

    if (tid == 0) qcnt = 0;
    if (tid < NWARP) sbest[tid] = 0;

    float px_ = 0.f, py_ = 0.f, ra = 0.f;
    if (valid) {
        const float* pb = box_pred + p * 7;
        px_ = pb[0]; py_ = pb[1];
        float hax = 0.5f * pb[3], hay = 0.5f * pb[4];
        float sa, ca;
        __sincosf(pb[6], &sa, &ca);
        ra = sqrtf(hax * hax + hay * hay);
        if (lane == 0) {
            float* sp = spred[slot];
            const float lx[4] = {hax, -hax, -hax, hax};
            const float ly[4] = {hay, hay, -hay, -hay};
            #pragma unroll
            for (int k = 0; k < 4; k++) {
                sp[k]     = px_ + ca * lx[k] - sa * ly[k];
                sp[4 + k] = py_ + sa * lx[k] + ca * ly[k];
            }
            sp[8] = px_; sp[9] = py_;
            sp[10] = hax; sp[11] = hay;
            sp[12] = sa;  sp[13] = ca;
            sp[14] = 4.0f * hax * hay;
        }
    }
    __syncthreads();   // spred + qcnt visible

    // ---- Phase 1: scan candidate cells, block-compact survivors ----
    if (valid) {
        float rbmax = g_rbmax;
        int R = (int)ceilf((ra + rbmax) * INVCEL);
        int pcx = clampi((int)floorf((px_ - WMIN) * INVCEL), 0, G - 1);
        int pcy = clampi((int)floorf((py_ - WMIN) * INVCEL), 0, G - 1);
        int cx0 = clampi(pcx - R, 0, G - 1), cx1 = clampi(pcx + R, 0, G - 1);
        int cy0 = clampi(pcy - R, 0, G - 1), cy1 = clampi(pcy + R, 0, G - 1);

        for (int cy = cy0; cy <= cy1; cy++) {
            int s = g_start[cy * G + cx0];
            int e = g_start[cy * G + cx1 + 1];
            for (int base = s; base < e; base += 32) {
                int idx = base + lane;
                bool ok = false;
                int j = 0;
                if (idx < e) {
                    j = g_list[idx];
                    float4 A4 = __ldg(&g_gtA[j]);
                    float ddx = A4.x - px_, ddy = A4.y - py_;
                    float rr = ra + A4.z;
                    ok = (ddx * ddx + ddy * ddy <= rr * rr);
                }
                unsigned m = __ballot_sync(0xffffffffu, ok);
                if (m) {
                    int nsurv = __popc(m);
                    int b0 = 0;
                    if (lane == 0) b0 = atomicAdd(&qcnt, nsurv);
                    b0 = __shfl_sync(0xffffffffu, b0, 0);
                    if (ok) {
                        int pos = b0 + __popc(m & ((1u << lane) - 1u));
                        if (pos < QCAP) {
                            q[pos] = (unsigned short)((slot << 10) | j);
                        } else {
                            // overflow fallback (statistically never)
                            float iou = pair_iou(spred[slot],
                                                 __ldg(&g_gtA[j]),
                                                 __ldg(&g_gtB[j]));
                            atomicMax(&sbest[slot], __float_as_int(iou));
                        }
                    }
                }
            }
        }
    }
    __syncthreads();

    // ---- Phase 2: dense block-wide clip over survivors ----
    int total = qcnt < QCAP ? qcnt : QCAP;
    for (int k = tid; k < total; k += TPB) {
        int e  = q[k];
        int sl = e >> 10;
        int j  = e & 1023;
        float iou = pair_iou(spred[sl], __ldg(&g_gtA[j]), __ldg(&g_gtB[j]));
        atomicMax(&sbest[sl], __float_as_int(iou));
    }
    __syncthreads();

    // ---- Finalize: warp 0 sums this block's loss terms ----
    if (slot == 0) {
        float term = 0.0f;
        if (lane < NWARP) {
            int pp = blockIdx.x * NWARP + lane;
            if (pp < N) {
                float mx = __int_as_float(sbest[lane]);
                float target = 2.0f * mx - 1.0f;
                term = fabsf(__ldg(&iou_pred[pp]) - target);
            }
        }
        #pragma unroll
        for (int o = 16; o > 0; o >>= 1)
            term += __shfl_xor_sync(0xffffffffu, term, o);

        if (lane == 0) {
            atomicAdd(&g_acc, term);
            __threadfence();
            unsigned t = atomicAdd(&g_done, 1);
            if (t == gridDim.x - 1) {
                float v = atomicAdd(&g_acc, 0.0f);
                int iv = *(const int*)ntp_raw;
                float fv = __int_as_float(iv);
                float ntp = (iv > 0 && iv < 100000000) ? (float)iv : fv;
                out[0] = v / (ntp + 1e-4f);
                for (int i = 1; i < out_size; i++) out[i] = 0.0f;
                g_acc = 0.0f;
                __threadfence();
                g_done = 0;
            }
        }
    }
}

extern "C" void kernel_launch(void* const* d_in, const int* in_sizes, int n_in,
                              void* d_out, int out_size) {
    const float* iou_pred = (const float*)d_in[0];
    const float* box_pred = (const float*)d_in[1];
    const float* box_gt   = (const float*)d_in[2];
    const void*  ntp      = d_in[3];

    int N = in_sizes[1] / 7;
    int M = in_sizes[2] / 7;
    if (M > MAXM) M = MAXM;

    float* out = (float*)d_out;

    prep_kernel<<<1, 256>>>(box_gt, M);

    int grid = (N + NWARP - 1) / NWARP;   // 256 blocks for N=2048
    iou_loss_kernel<<<grid, TPB>>>(iou_pred, box_pred, ntp, out,
                                   N, M, out_size);
}